// round 10
// baseline (speedup 1.0000x reference)
#include <cuda_runtime.h>
#include <cuda_fp16.h>
#include <mma.h>
#include <math.h>
#include <cstdint>
#include <stdint.h>

using namespace nvcuda;

// Problem dims
#define Bb   8192
#define Tt   8
#define Vv   65
#define Cc   512
#define Hh   8
#define HSs  64
#define Ll   6
#define DFFd 2048
#define NT   (Bb*Tt)   // 65536 tokens

// ---------------- scratch (device globals) ----------------
__device__ float  g_x  [(size_t)NT*Cc];          // residual stream (fp32)
__device__ __half g_xh [(size_t)NT*Cc];          // half copy of x (GEMM A)
__device__ __half g_qkvh[(size_t)NT*3*Cc];       // q|k|v (half)
__device__ __half g_aoh[(size_t)NT*Cc];          // attention out (half)
__device__ float  g_y  [(size_t)NT*Cc];          // pre-LN gemm out (fp32)
__device__ __half g_hh [(size_t)NT*DFFd];        // MLP hidden (half)
__device__ __half g_wqkvh[(size_t)Ll*Cc*3*Cc];   // qkv weights (C,1536)
__device__ __half g_wprojh[(size_t)Ll*Cc*Cc];    // proj (C,C)
__device__ __half g_w1h[(size_t)Ll*Cc*DFFd];     // w1 (C,DFF)
__device__ __half g_w2h[(size_t)Ll*DFFd*Cc];     // w2 (DFF,C)

__device__ __forceinline__ void cp16(void* smem, const void* gmem) {
    unsigned int s = (unsigned int)__cvta_generic_to_shared(smem);
    asm volatile("cp.async.ca.shared.global [%0], [%1], 16;\n" :: "r"(s), "l"(gmem));
}
#define CP_COMMIT() asm volatile("cp.async.commit_group;\n" ::: "memory")
#define CP_WAIT1()  asm volatile("cp.async.wait_group 1;\n" ::: "memory")

// ---------------- weight prep ------------------------------------------------------
__global__ void pack_qkv_h(const float* __restrict__ wq,
                           const float* __restrict__ wk,
                           const float* __restrict__ wv) {
    int i = blockIdx.x * 256 + threadIdx.x;
    if (i >= Ll*Cc*3*Cc) return;
    int col = i % (3*Cc);
    int c   = (i / (3*Cc)) % Cc;
    int l   = i / (3*Cc*Cc);
    const float* src; int j;
    if (col < Cc)        { src = wq; j = col; }
    else if (col < 2*Cc) { src = wk; j = col - Cc; }
    else                 { src = wv; j = col - 2*Cc; }
    int h = j / HSs, d = j % HSs;
    g_wqkvh[i] = __float2half_rn(src[(((size_t)l*Hh + h)*Cc + c)*HSs + d]);
}

__global__ void half_copy(const float* __restrict__ src, __half* __restrict__ dst, int n2) {
    int i = blockIdx.x * 256 + threadIdx.x;
    if (i >= n2) return;
    float2 v = ((const float2*)src)[i];
    ((__half2*)dst)[i] = __floats2half2_rn(v.x, v.y);
}

// ---------------- embedding: fp32 x + half copy ------------------------------------
__global__ void embed_kernel(const int* __restrict__ idx,
                             const float* __restrict__ tok,
                             const float* __restrict__ pos) {
    int i = blockIdx.x * 256 + threadIdx.x;
    if (i >= NT*Cc/4) return;
    int c4 = i % (Cc/4);
    int token = i / (Cc/4);
    int t = token & (Tt-1);
    float4 a = ((const float4*)tok)[(size_t)idx[token]*(Cc/4) + c4];
    float4 p = ((const float4*)pos)[(size_t)t*(Cc/4) + c4];
    float4 v = make_float4(a.x+p.x, a.y+p.y, a.z+p.z, a.w+p.w);
    ((float4*)g_x)[i] = v;
    ((__half2*)g_xh)[i*2]   = __floats2half2_rn(v.x, v.y);
    ((__half2*)g_xh)[i*2+1] = __floats2half2_rn(v.z, v.w);
}

// ---------------- FP16 wmma GEMM, BK=64, 3-stage cp.async, 1 bar/iter --------------
// Cf/Ch(M,N) = A(M,K)h @ B(K,N)h (+bias); relu optional. Either output may be null.
// M%128==0, N%256==0, K%64==0, K>=128.
#define BM 128
#define BN 256
#define BK 64
#define APADH 72       // halves per A row (64+8)
#define BPADH 272      // halves per B row (256+16)
#define A_STGH (BM*APADH)      // 9216 halves  (18 KB)
#define B_STGH (BK*BPADH)      // 17408 halves (34 KB)
#define SMEM_DYN (3*(A_STGH + B_STGH)*2)   // 159744 bytes

__global__ void __launch_bounds__(256)
gemm_h(const __half* __restrict__ A, const __half* __restrict__ B,
       const float* __restrict__ bias,
       float* __restrict__ Cf, __half* __restrict__ Ch,
       int M, int N, int K, int relu)
{
    extern __shared__ __half hsm[];
    __half* As = hsm;                 // [3][BM][APADH]
    __half* Bs = hsm + 3*A_STGH;      // [3][BK][BPADH]
    __shared__ float stage[8][16][16];

    int tid  = threadIdx.x;
    int warp = tid >> 5, lane = tid & 31;
    int wm = warp >> 2, wn = warp & 3;          // 2x4 warps; warp tile 64x64
    int bm = blockIdx.y * BM, bn = blockIdx.x * BN;
    int nt = K / BK;

    wmma::fragment<wmma::accumulator,16,16,16,float> acc[4][4];
    #pragma unroll
    for (int i = 0; i < 4; i++)
        #pragma unroll
        for (int j = 0; j < 4; j++)
            wmma::fill_fragment(acc[i][j], 0.0f);

    auto issue_stage = [&](int st, int k0) {
        __half* as = As + st*A_STGH;
        __half* bs = Bs + st*B_STGH;
        #pragma unroll
        for (int i = 0; i < 4; i++) {           // A: 128 rows x 8 chunks
            int idx2 = tid + 256*i;
            int row = idx2 >> 3, c8 = (idx2 & 7) * 8;
            cp16(&as[row*APADH + c8], &A[(size_t)(bm+row)*K + k0 + c8]);
        }
        #pragma unroll
        for (int i = 0; i < 8; i++) {           // B: 64 rows x 32 chunks
            int idx2 = tid + 256*i;
            int row = idx2 >> 5, c8 = (idx2 & 31) * 8;
            cp16(&bs[row*BPADH + c8], &B[(size_t)(k0+row)*N + bn + c8]);
        }
    };

    issue_stage(0, 0);  CP_COMMIT();
    issue_stage(1, BK); CP_COMMIT();

    for (int i = 0; i < nt; i++) {
        int s = i % 3;
        CP_WAIT1();              // stage i landed
        __syncthreads();         // all warps done with stage i-1 -> buffer (i+2)%3 free
        if (i + 2 < nt) {
            int ns = i + 2; ns -= (ns / 3) * 3;
            issue_stage(ns, (i + 2) * BK);
        }
        CP_COMMIT();             // exactly one group per iter

        const __half* as = As + s*A_STGH;
        const __half* bs = Bs + s*B_STGH;
        #pragma unroll
        for (int kk = 0; kk < 4; kk++) {
            wmma::fragment<wmma::matrix_a,16,16,16,__half,wmma::row_major> af[4];
            wmma::fragment<wmma::matrix_b,16,16,16,__half,wmma::row_major> bf[4];
            #pragma unroll
            for (int i2 = 0; i2 < 4; i2++)
                wmma::load_matrix_sync(af[i2], &as[(wm*64 + i2*16)*APADH + kk*16], APADH);
            #pragma unroll
            for (int j = 0; j < 4; j++)
                wmma::load_matrix_sync(bf[j], &bs[(kk*16)*BPADH + wn*64 + j*16], BPADH);
            #pragma unroll
            for (int i2 = 0; i2 < 4; i2++)
                #pragma unroll
                for (int j = 0; j < 4; j++)
                    wmma::mma_sync(acc[i2][j], af[i2], bf[j], acc[i2][j]);
        }
    }
    __syncthreads();

    // epilogue
    #pragma unroll
    for (int i = 0; i < 4; i++) {
        #pragma unroll
        for (int j = 0; j < 4; j++) {
            wmma::store_matrix_sync(&stage[warp][0][0], acc[i][j], 16, wmma::mem_row_major);
            __syncwarp();
            int grow0 = bm + wm*64 + i*16;
            int gcol0 = bn + wn*64 + j*16;
            #pragma unroll
            for (int e = 0; e < 2; e++) {
                int idx2 = e*32 + lane;
                int r = idx2 >> 2, c4 = (idx2 & 3) * 4;
                float4 v = *(float4*)&stage[warp][r][c4];
                if (bias) {
                    float4 bv = *(const float4*)&bias[gcol0 + c4];
                    v.x += bv.x; v.y += bv.y; v.z += bv.z; v.w += bv.w;
                }
                if (relu) {
                    v.x = fmaxf(v.x, 0.f); v.y = fmaxf(v.y, 0.f);
                    v.z = fmaxf(v.z, 0.f); v.w = fmaxf(v.w, 0.f);
                }
                size_t off = (size_t)(grow0 + r)*N + gcol0 + c4;
                if (Cf) *(float4*)&Cf[off] = v;
                if (Ch) {
                    *(__half2*)&Ch[off]     = __floats2half2_rn(v.x, v.y);
                    *(__half2*)&Ch[off + 2] = __floats2half2_rn(v.z, v.w);
                }
            }
            __syncwarp();
        }
    }
}

// ---------------- attention: one warp per (b,h); T=8, HS=64; scale = C^-0.5 -------
__global__ void __launch_bounds__(128)
attn_kernel() {
    __shared__ float sq[4][8][66], sk[4][8][66], sv[4][8][66];
    __shared__ float satt[4][8][9];
    int warp = threadIdx.x >> 5, lane = threadIdx.x & 31;
    int bh = blockIdx.x * 4 + warp;
    int b = bh >> 3, h = bh & 7;
    size_t tok0 = (size_t)b * Tt;

    #pragma unroll
    for (int t = 0; t < 8; t++) {
        const __half2* row2 = (const __half2*)&g_qkvh[(tok0 + t) * (3*Cc)];
        float2 qf = __half22float2(row2[          h*32 + lane]);
        float2 kf = __half22float2(row2[Cc/2    + h*32 + lane]);
        float2 vf = __half22float2(row2[Cc      + h*32 + lane]);
        sq[warp][t][2*lane] = qf.x; sq[warp][t][2*lane+1] = qf.y;
        sk[warp][t][2*lane] = kf.x; sk[warp][t][2*lane+1] = kf.y;
        sv[warp][t][2*lane] = vf.x; sv[warp][t][2*lane+1] = vf.y;
    }
    __syncwarp();

    const float scale = 0.044194173824159216f;   // 512^-0.5
    #pragma unroll
    for (int p = lane; p < 64; p += 32) {
        int t = p >> 3, sIdx = p & 7;
        float acc = 0.f;
        #pragma unroll
        for (int d = 0; d < 64; d++) acc += sq[warp][t][d] * sk[warp][sIdx][d];
        satt[warp][t][sIdx] = (sIdx <= t) ? acc * scale : 0.0f;
    }
    __syncwarp();

    if (lane < 8) {
        int t = lane;
        float m = -1e30f;
        for (int sIdx = 0; sIdx <= t; sIdx++) m = fmaxf(m, satt[warp][t][sIdx]);
        float e[8]; float sum = 0.f;
        #pragma unroll
        for (int sIdx = 0; sIdx < 8; sIdx++) {
            e[sIdx] = (sIdx <= t) ? __expf(satt[warp][t][sIdx] - m) : 0.0f;
            sum += e[sIdx];
        }
        float inv = 1.0f / sum;
        #pragma unroll
        for (int sIdx = 0; sIdx < 8; sIdx++) satt[warp][t][sIdx] = e[sIdx] * inv;
    }
    __syncwarp();

    #pragma unroll
    for (int t = 0; t < 8; t++) {
        float a0 = 0.f, a1 = 0.f;
        #pragma unroll
        for (int sIdx = 0; sIdx < 8; sIdx++) {
            float w = satt[warp][t][sIdx];
            a0 += w * sv[warp][sIdx][lane];
            a1 += w * sv[warp][sIdx][lane + 32];
        }
        g_aoh[(tok0 + t)*Cc + h*64 + lane]      = __float2half_rn(a0);
        g_aoh[(tok0 + t)*Cc + h*64 + lane + 32] = __float2half_rn(a1);
    }
}

// ---------------- fused residual add + LayerNorm: fp32 x + half copy ---------------
__global__ void __launch_bounds__(256)
add_ln_kernel(const float* __restrict__ y,
              const float* __restrict__ gamma, const float* __restrict__ beta) {
    int warp = threadIdx.x >> 5, lane = threadIdx.x & 31;
    size_t row = (size_t)blockIdx.x * 8 + warp;
    float*  xr = &g_x [row * Cc];
    __half* xh = &g_xh[row * Cc];
    const float* yr = &y[row * Cc];
    float v[16];
    float s = 0.f;
    #pragma unroll
    for (int i = 0; i < 16; i++) {
        v[i] = xr[lane + 32*i] + yr[lane + 32*i];
        s += v[i];
    }
    #pragma unroll
    for (int off = 16; off > 0; off >>= 1) s += __shfl_xor_sync(0xFFFFFFFFu, s, off);
    float mu = s * (1.0f / Cc);
    float var = 0.f;
    #pragma unroll
    for (int i = 0; i < 16; i++) { float d = v[i] - mu; var += d * d; }
    #pragma unroll
    for (int off = 16; off > 0; off >>= 1) var += __shfl_xor_sync(0xFFFFFFFFu, var, off);
    var *= (1.0f / Cc);
    float r = rsqrtf(var + 1e-5f);
    #pragma unroll
    for (int i = 0; i < 16; i++) {
        int c = lane + 32*i;
        float o = (v[i] - mu) * r * gamma[c] + beta[c];
        xr[c] = o;
        xh[c] = __float2half_rn(o);
    }
}

// ---------------- logits: (NT,512) @ (512,65) + b  (full fp32) ---------------------
__global__ void __launch_bounds__(256)
logits_kernel(const float* __restrict__ lmw, const float* __restrict__ lmb,
              float* __restrict__ out) {
    __shared__ float As2[16][512];
    size_t row0 = (size_t)blockIdx.x * 16;
    for (int i = threadIdx.x; i < 16*512; i += 256)
        As2[i >> 9][i & 511] = g_x[(row0 + (i >> 9))*Cc + (i & 511)];
    __syncthreads();
    for (int idx2 = threadIdx.x; idx2 < 16*Vv; idx2 += 256) {
        int r = idx2 / Vv, c = idx2 % Vv;
        float s = lmb[c];
        #pragma unroll 8
        for (int k = 0; k < 512; k++) s += As2[r][k] * lmw[k*Vv + c];
        out[(row0 + r)*Vv + c] = s;
    }
}

// ---------------- host launch ------------------------------------------------------
extern "C" void kernel_launch(void* const* d_in, const int* in_sizes, int n_in,
                              void* d_out, int out_size) {
    const int*   idx    = (const int*)  d_in[0];
    const float* tok    = (const float*)d_in[1];
    const float* pos    = (const float*)d_in[2];
    const float* wq     = (const float*)d_in[3];
    const float* wk     = (const float*)d_in[4];
    const float* wv     = (const float*)d_in[5];
    const float* proj_w = (const float*)d_in[6];
    const float* proj_b = (const float*)d_in[7];
    const float* w1     = (const float*)d_in[8];
    const float* b1     = (const float*)d_in[9];
    const float* w2     = (const float*)d_in[10];
    const float* b2     = (const float*)d_in[11];
    const float* ln1g   = (const float*)d_in[12];
    const float* ln1b   = (const float*)d_in[13];
    const float* ln2g   = (const float*)d_in[14];
    const float* ln2b   = (const float*)d_in[15];
    const float* lm_w   = (const float*)d_in[16];
    const float* lm_b   = (const float*)d_in[17];
    float* out = (float*)d_out;

    cudaFuncSetAttribute(gemm_h, cudaFuncAttributeMaxDynamicSharedMemorySize, SMEM_DYN);

    float *x, *y;
    __half *xh, *qkvh, *aoh, *hh, *wqkvh, *wprojh, *w1h, *w2h;
    cudaGetSymbolAddress((void**)&x,     g_x);
    cudaGetSymbolAddress((void**)&xh,    g_xh);
    cudaGetSymbolAddress((void**)&qkvh,  g_qkvh);
    cudaGetSymbolAddress((void**)&aoh,   g_aoh);
    cudaGetSymbolAddress((void**)&y,     g_y);
    cudaGetSymbolAddress((void**)&hh,    g_hh);
    cudaGetSymbolAddress((void**)&wqkvh, g_wqkvh);
    cudaGetSymbolAddress((void**)&wprojh,g_wprojh);
    cudaGetSymbolAddress((void**)&w1h,   g_w1h);
    cudaGetSymbolAddress((void**)&w2h,   g_w2h);

    pack_qkv_h<<<(Ll*Cc*3*Cc + 255)/256, 256>>>(wq, wk, wv);
    half_copy<<<(Ll*Cc*Cc/2 + 255)/256, 256>>>(proj_w, wprojh, Ll*Cc*Cc/2);
    half_copy<<<(Ll*Cc*DFFd/2 + 255)/256, 256>>>(w1, w1h, Ll*Cc*DFFd/2);
    half_copy<<<(Ll*DFFd*Cc/2 + 255)/256, 256>>>(w2, w2h, Ll*DFFd*Cc/2);
    embed_kernel<<<(NT*Cc/4 + 255)/256, 256>>>(idx, tok, pos);

    for (int l = 0; l < Ll; l++) {
        // QKV: (NT,512)h @ (512,1536)h -> half
        gemm_h<<<dim3(3*Cc/BN, NT/BM), 256, SMEM_DYN>>>(
            xh, wqkvh + (size_t)l*Cc*3*Cc, nullptr, nullptr, qkvh, NT, 3*Cc, Cc, 0);
        // attention -> half ao
        attn_kernel<<<Bb*Hh/4, 128>>>();
        // proj: (NT,512)h @ (512,512)h + b -> fp32 y
        gemm_h<<<dim3(Cc/BN, NT/BM), 256, SMEM_DYN>>>(
            aoh, wprojh + (size_t)l*Cc*Cc, proj_b + (size_t)l*Cc, y, nullptr, NT, Cc, Cc, 0);
        // x = LN(x + y); writes fp32 + half
        add_ln_kernel<<<NT/8, 256>>>(y, ln1g + (size_t)l*Cc, ln1b + (size_t)l*Cc);
        // MLP up: (NT,512)h @ (512,2048)h + b, relu -> half h
        gemm_h<<<dim3(DFFd/BN, NT/BM), 256, SMEM_DYN>>>(
            xh, w1h + (size_t)l*Cc*DFFd, b1 + (size_t)l*DFFd, nullptr, hh, NT, DFFd, Cc, 1);
        // MLP down: (NT,2048)h @ (2048,512)h + b -> fp32 y
        gemm_h<<<dim3(Cc/BN, NT/BM), 256, SMEM_DYN>>>(
            hh, w2h + (size_t)l*DFFd*Cc, b2 + (size_t)l*Cc, y, nullptr, NT, Cc, DFFd, 0);
        // x = LN(x + y)
        add_ln_kernel<<<NT/8, 256>>>(y, ln2g + (size_t)l*Cc, ln2b + (size_t)l*Cc);
    }

    logits_kernel<<<NT/16, 256>>>(lm_w, lm_b, out);
}

// round 11
// speedup vs baseline: 1.0529x; 1.0529x over previous
#include <cuda_runtime.h>
#include <cuda_fp16.h>
#include <mma.h>
#include <math.h>
#include <cstdint>
#include <stdint.h>

using namespace nvcuda;

// Problem dims
#define Bb   8192
#define Tt   8
#define Vv   65
#define Cc   512
#define Hh   8
#define HSs  64
#define Ll   6
#define DFFd 2048
#define NT   (Bb*Tt)   // 65536 tokens

// ---------------- scratch (device globals) ----------------
__device__ float  g_x  [(size_t)NT*Cc];          // residual stream (fp32)
__device__ __half g_xh [(size_t)NT*Cc];          // half copy of x (GEMM A)
__device__ __half g_qkvh[(size_t)NT*3*Cc];       // q|k|v (half)
__device__ __half g_aoh[(size_t)NT*Cc];          // attention out (half)
__device__ float  g_y  [(size_t)NT*Cc];          // pre-LN gemm out (fp32)
__device__ __half g_hh [(size_t)NT*DFFd];        // MLP hidden (half)
__device__ __half g_wqkvh[(size_t)Ll*Cc*3*Cc];   // qkv weights (C,1536)
__device__ __half g_wprojh[(size_t)Ll*Cc*Cc];    // proj (C,C)
__device__ __half g_w1h[(size_t)Ll*Cc*DFFd];     // w1 (C,DFF)
__device__ __half g_w2h[(size_t)Ll*DFFd*Cc];     // w2 (DFF,C)

__device__ __forceinline__ void cp16(void* smem, const void* gmem) {
    unsigned int s = (unsigned int)__cvta_generic_to_shared(smem);
    asm volatile("cp.async.ca.shared.global [%0], [%1], 16;\n" :: "r"(s), "l"(gmem));
}
#define CP_COMMIT() asm volatile("cp.async.commit_group;\n" ::: "memory")
#define CP_WAIT1()  asm volatile("cp.async.wait_group 1;\n" ::: "memory")

// ---------------- weight prep ------------------------------------------------------
__global__ void pack_qkv_h(const float* __restrict__ wq,
                           const float* __restrict__ wk,
                           const float* __restrict__ wv) {
    int i = blockIdx.x * 256 + threadIdx.x;
    if (i >= Ll*Cc*3*Cc) return;
    int col = i % (3*Cc);
    int c   = (i / (3*Cc)) % Cc;
    int l   = i / (3*Cc*Cc);
    const float* src; int j;
    if (col < Cc)        { src = wq; j = col; }
    else if (col < 2*Cc) { src = wk; j = col - Cc; }
    else                 { src = wv; j = col - 2*Cc; }
    int h = j / HSs, d = j % HSs;
    g_wqkvh[i] = __float2half_rn(src[(((size_t)l*Hh + h)*Cc + c)*HSs + d]);
}

__global__ void half_copy(const float* __restrict__ src, __half* __restrict__ dst, int n2) {
    int i = blockIdx.x * 256 + threadIdx.x;
    if (i >= n2) return;
    float2 v = ((const float2*)src)[i];
    ((__half2*)dst)[i] = __floats2half2_rn(v.x, v.y);
}

// ---------------- embedding: fp32 x + half copy ------------------------------------
__global__ void embed_kernel(const int* __restrict__ idx,
                             const float* __restrict__ tok,
                             const float* __restrict__ pos) {
    int i = blockIdx.x * 256 + threadIdx.x;
    if (i >= NT*Cc/4) return;
    int c4 = i % (Cc/4);
    int token = i / (Cc/4);
    int t = token & (Tt-1);
    float4 a = ((const float4*)tok)[(size_t)idx[token]*(Cc/4) + c4];
    float4 p = ((const float4*)pos)[(size_t)t*(Cc/4) + c4];
    float4 v = make_float4(a.x+p.x, a.y+p.y, a.z+p.z, a.w+p.w);
    ((float4*)g_x)[i] = v;
    ((__half2*)g_xh)[i*2]   = __floats2half2_rn(v.x, v.y);
    ((__half2*)g_xh)[i*2+1] = __floats2half2_rn(v.z, v.w);
}

// ---------------- FP16 wmma GEMM, BK=64, 3-stage cp.async --------------------------
// Cf/Ch(M,N) = A(M,K)h @ B(K,N)h (+bias); relu optional. Either output may be null.
// M%128==0, N%256==0, K%64==0, K>=128.
#define BM 128
#define BN 256
#define BK 64
#define APADH 72       // A row stride 144B: 144%128=16 -> conflict-free LDSM
#define BPADH 264      // B row stride 528B: 528%128=16 -> conflict-free LDSM (was 272 = 2-way)
#define A_STGH (BM*APADH)      // 9216 halves
#define B_STGH (BK*BPADH)      // 16896 halves
#define SMEM_DYN (3*(A_STGH + B_STGH)*2)   // 156672 bytes

__global__ void __launch_bounds__(256)
gemm_h(const __half* __restrict__ A, const __half* __restrict__ B,
       const float* __restrict__ bias,
       float* __restrict__ Cf, __half* __restrict__ Ch,
       int M, int N, int K, int relu)
{
    extern __shared__ __half hsm[];
    __half* As = hsm;                 // [3][BM][APADH]
    __half* Bs = hsm + 3*A_STGH;      // [3][BK][BPADH]
    __shared__ float stage[8][16*20]; // ldm=20 floats (80B stride, conflict-free)

    int tid  = threadIdx.x;
    int warp = tid >> 5, lane = tid & 31;
    int wm = warp >> 2, wn = warp & 3;          // 2x4 warps; warp tile 64x64
    int bm = blockIdx.y * BM, bn = blockIdx.x * BN;
    int nt = K / BK;

    wmma::fragment<wmma::accumulator,16,16,16,float> acc[4][4];
    #pragma unroll
    for (int i = 0; i < 4; i++)
        #pragma unroll
        for (int j = 0; j < 4; j++)
            wmma::fill_fragment(acc[i][j], 0.0f);

    auto issue_stage = [&](int st, int k0) {
        __half* as = As + st*A_STGH;
        __half* bs = Bs + st*B_STGH;
        #pragma unroll
        for (int i = 0; i < 4; i++) {           // A: 128 rows x 8 chunks
            int idx2 = tid + 256*i;
            int row = idx2 >> 3, c8 = (idx2 & 7) * 8;
            cp16(&as[row*APADH + c8], &A[(size_t)(bm+row)*K + k0 + c8]);
        }
        #pragma unroll
        for (int i = 0; i < 8; i++) {           // B: 64 rows x 32 chunks
            int idx2 = tid + 256*i;
            int row = idx2 >> 5, c8 = (idx2 & 31) * 8;
            cp16(&bs[row*BPADH + c8], &B[(size_t)(k0+row)*N + bn + c8]);
        }
    };

    issue_stage(0, 0);  CP_COMMIT();
    issue_stage(1, BK); CP_COMMIT();

    for (int i = 0; i < nt; i++) {
        int s = i % 3;
        CP_WAIT1();              // stage i landed
        __syncthreads();         // all warps done with stage i-1 -> buffer (i+2)%3 free
        if (i + 2 < nt) {
            int ns = i + 2; ns -= (ns / 3) * 3;
            issue_stage(ns, (i + 2) * BK);
        }
        CP_COMMIT();             // exactly one group per iter

        const __half* as = As + s*A_STGH;
        const __half* bs = Bs + s*B_STGH;
        #pragma unroll
        for (int kk = 0; kk < 4; kk++) {
            wmma::fragment<wmma::matrix_a,16,16,16,__half,wmma::row_major> af[4];
            wmma::fragment<wmma::matrix_b,16,16,16,__half,wmma::row_major> bf[4];
            #pragma unroll
            for (int i2 = 0; i2 < 4; i2++)
                wmma::load_matrix_sync(af[i2], &as[(wm*64 + i2*16)*APADH + kk*16], APADH);
            #pragma unroll
            for (int j = 0; j < 4; j++)
                wmma::load_matrix_sync(bf[j], &bs[(kk*16)*BPADH + wn*64 + j*16], BPADH);
            #pragma unroll
            for (int i2 = 0; i2 < 4; i2++)
                #pragma unroll
                for (int j = 0; j < 4; j++)
                    wmma::mma_sync(acc[i2][j], af[i2], bf[j], acc[i2][j]);
        }
    }
    __syncthreads();

    // epilogue
    #pragma unroll
    for (int i = 0; i < 4; i++) {
        #pragma unroll
        for (int j = 0; j < 4; j++) {
            wmma::store_matrix_sync(&stage[warp][0], acc[i][j], 20, wmma::mem_row_major);
            __syncwarp();
            int grow0 = bm + wm*64 + i*16;
            int gcol0 = bn + wn*64 + j*16;
            #pragma unroll
            for (int e = 0; e < 2; e++) {
                int idx2 = e*32 + lane;
                int r = idx2 >> 2, c4 = (idx2 & 3) * 4;
                float4 v = *(float4*)&stage[warp][r*20 + c4];
                if (bias) {
                    float4 bv = *(const float4*)&bias[gcol0 + c4];
                    v.x += bv.x; v.y += bv.y; v.z += bv.z; v.w += bv.w;
                }
                if (relu) {
                    v.x = fmaxf(v.x, 0.f); v.y = fmaxf(v.y, 0.f);
                    v.z = fmaxf(v.z, 0.f); v.w = fmaxf(v.w, 0.f);
                }
                size_t off = (size_t)(grow0 + r)*N + gcol0 + c4;
                if (Cf) *(float4*)&Cf[off] = v;
                if (Ch) {
                    *(__half2*)&Ch[off]     = __floats2half2_rn(v.x, v.y);
                    *(__half2*)&Ch[off + 2] = __floats2half2_rn(v.z, v.w);
                }
            }
            __syncwarp();
        }
    }
}

// ---------------- attention: one warp per (b,h); T=8, HS=64; scale = C^-0.5 -------
__global__ void __launch_bounds__(128)
attn_kernel() {
    __shared__ float sq[4][8][66], sk[4][8][66], sv[4][8][66];
    __shared__ float satt[4][8][9];
    int warp = threadIdx.x >> 5, lane = threadIdx.x & 31;
    int bh = blockIdx.x * 4 + warp;
    int b = bh >> 3, h = bh & 7;
    size_t tok0 = (size_t)b * Tt;

    #pragma unroll
    for (int t = 0; t < 8; t++) {
        const __half2* row2 = (const __half2*)&g_qkvh[(tok0 + t) * (3*Cc)];
        float2 qf = __half22float2(row2[          h*32 + lane]);
        float2 kf = __half22float2(row2[Cc/2    + h*32 + lane]);
        float2 vf = __half22float2(row2[Cc      + h*32 + lane]);
        sq[warp][t][2*lane] = qf.x; sq[warp][t][2*lane+1] = qf.y;
        sk[warp][t][2*lane] = kf.x; sk[warp][t][2*lane+1] = kf.y;
        sv[warp][t][2*lane] = vf.x; sv[warp][t][2*lane+1] = vf.y;
    }
    __syncwarp();

    const float scale = 0.044194173824159216f;   // 512^-0.5
    #pragma unroll
    for (int p = lane; p < 64; p += 32) {
        int t = p >> 3, sIdx = p & 7;
        float acc = 0.f;
        #pragma unroll
        for (int d = 0; d < 64; d++) acc += sq[warp][t][d] * sk[warp][sIdx][d];
        satt[warp][t][sIdx] = (sIdx <= t) ? acc * scale : 0.0f;
    }
    __syncwarp();

    if (lane < 8) {
        int t = lane;
        float m = -1e30f;
        for (int sIdx = 0; sIdx <= t; sIdx++) m = fmaxf(m, satt[warp][t][sIdx]);
        float e[8]; float sum = 0.f;
        #pragma unroll
        for (int sIdx = 0; sIdx < 8; sIdx++) {
            e[sIdx] = (sIdx <= t) ? __expf(satt[warp][t][sIdx] - m) : 0.0f;
            sum += e[sIdx];
        }
        float inv = 1.0f / sum;
        #pragma unroll
        for (int sIdx = 0; sIdx < 8; sIdx++) satt[warp][t][sIdx] = e[sIdx] * inv;
    }
    __syncwarp();

    #pragma unroll
    for (int t = 0; t < 8; t++) {
        float a0 = 0.f, a1 = 0.f;
        #pragma unroll
        for (int sIdx = 0; sIdx < 8; sIdx++) {
            float w = satt[warp][t][sIdx];
            a0 += w * sv[warp][sIdx][lane];
            a1 += w * sv[warp][sIdx][lane + 32];
        }
        g_aoh[(tok0 + t)*Cc + h*64 + lane]      = __float2half_rn(a0);
        g_aoh[(tok0 + t)*Cc + h*64 + lane + 32] = __float2half_rn(a1);
    }
}

// ---------------- fused residual add + LayerNorm: fp32 x + half copy ---------------
__global__ void __launch_bounds__(256)
add_ln_kernel(const float* __restrict__ y,
              const float* __restrict__ gamma, const float* __restrict__ beta) {
    int warp = threadIdx.x >> 5, lane = threadIdx.x & 31;
    size_t row = (size_t)blockIdx.x * 8 + warp;
    float*  xr = &g_x [row * Cc];
    __half* xh = &g_xh[row * Cc];
    const float* yr = &y[row * Cc];
    float v[16];
    float s = 0.f;
    #pragma unroll
    for (int i = 0; i < 16; i++) {
        v[i] = xr[lane + 32*i] + yr[lane + 32*i];
        s += v[i];
    }
    #pragma unroll
    for (int off = 16; off > 0; off >>= 1) s += __shfl_xor_sync(0xFFFFFFFFu, s, off);
    float mu = s * (1.0f / Cc);
    float var = 0.f;
    #pragma unroll
    for (int i = 0; i < 16; i++) { float d = v[i] - mu; var += d * d; }
    #pragma unroll
    for (int off = 16; off > 0; off >>= 1) var += __shfl_xor_sync(0xFFFFFFFFu, var, off);
    var *= (1.0f / Cc);
    float r = rsqrtf(var + 1e-5f);
    #pragma unroll
    for (int i = 0; i < 16; i++) {
        int c = lane + 32*i;
        float o = (v[i] - mu) * r * gamma[c] + beta[c];
        xr[c] = o;
        xh[c] = __float2half_rn(o);
    }
}

// ---------------- logits: (NT,512) @ (512,65) + b  (full fp32) ---------------------
__global__ void __launch_bounds__(256)
logits_kernel(const float* __restrict__ lmw, const float* __restrict__ lmb,
              float* __restrict__ out) {
    __shared__ float As2[16][512];
    size_t row0 = (size_t)blockIdx.x * 16;
    for (int i = threadIdx.x; i < 16*512; i += 256)
        As2[i >> 9][i & 511] = g_x[(row0 + (i >> 9))*Cc + (i & 511)];
    __syncthreads();
    for (int idx2 = threadIdx.x; idx2 < 16*Vv; idx2 += 256) {
        int r = idx2 / Vv, c = idx2 % Vv;
        float s = lmb[c];
        #pragma unroll 8
        for (int k = 0; k < 512; k++) s += As2[r][k] * lmw[k*Vv + c];
        out[(row0 + r)*Vv + c] = s;
    }
}

// ---------------- host launch ------------------------------------------------------
extern "C" void kernel_launch(void* const* d_in, const int* in_sizes, int n_in,
                              void* d_out, int out_size) {
    const int*   idx    = (const int*)  d_in[0];
    const float* tok    = (const float*)d_in[1];
    const float* pos    = (const float*)d_in[2];
    const float* wq     = (const float*)d_in[3];
    const float* wk     = (const float*)d_in[4];
    const float* wv     = (const float*)d_in[5];
    const float* proj_w = (const float*)d_in[6];
    const float* proj_b = (const float*)d_in[7];
    const float* w1     = (const float*)d_in[8];
    const float* b1     = (const float*)d_in[9];
    const float* w2     = (const float*)d_in[10];
    const float* b2     = (const float*)d_in[11];
    const float* ln1g   = (const float*)d_in[12];
    const float* ln1b   = (const float*)d_in[13];
    const float* ln2g   = (const float*)d_in[14];
    const float* ln2b   = (const float*)d_in[15];
    const float* lm_w   = (const float*)d_in[16];
    const float* lm_b   = (const float*)d_in[17];
    float* out = (float*)d_out;

    cudaFuncSetAttribute(gemm_h, cudaFuncAttributeMaxDynamicSharedMemorySize, SMEM_DYN);

    float *x, *y;
    __half *xh, *qkvh, *aoh, *hh, *wqkvh, *wprojh, *w1h, *w2h;
    cudaGetSymbolAddress((void**)&x,     g_x);
    cudaGetSymbolAddress((void**)&xh,    g_xh);
    cudaGetSymbolAddress((void**)&qkvh,  g_qkvh);
    cudaGetSymbolAddress((void**)&aoh,   g_aoh);
    cudaGetSymbolAddress((void**)&y,     g_y);
    cudaGetSymbolAddress((void**)&hh,    g_hh);
    cudaGetSymbolAddress((void**)&wqkvh, g_wqkvh);
    cudaGetSymbolAddress((void**)&wprojh,g_wprojh);
    cudaGetSymbolAddress((void**)&w1h,   g_w1h);
    cudaGetSymbolAddress((void**)&w2h,   g_w2h);

    // launch order: QKV gemm is launch #3 so the ncu capture window hits it
    pack_qkv_h<<<(Ll*Cc*3*Cc + 255)/256, 256>>>(wq, wk, wv);              // 1
    embed_kernel<<<(NT*Cc/4 + 255)/256, 256>>>(idx, tok, pos);            // 2
    gemm_h<<<dim3(3*Cc/BN, NT/BM), 256, SMEM_DYN>>>(                      // 3 (layer 0 QKV)
        xh, wqkvh, nullptr, nullptr, qkvh, NT, 3*Cc, Cc, 0);
    attn_kernel<<<Bb*Hh/4, 128>>>();                                      // 4
    half_copy<<<(Ll*Cc*Cc/2 + 255)/256, 256>>>(proj_w, wprojh, Ll*Cc*Cc/2);
    half_copy<<<(Ll*Cc*DFFd/2 + 255)/256, 256>>>(w1, w1h, Ll*Cc*DFFd/2);
    half_copy<<<(Ll*DFFd*Cc/2 + 255)/256, 256>>>(w2, w2h, Ll*DFFd*Cc/2);

    for (int l = 0; l < Ll; l++) {
        if (l > 0) {
            // QKV: (NT,512)h @ (512,1536)h -> half
            gemm_h<<<dim3(3*Cc/BN, NT/BM), 256, SMEM_DYN>>>(
                xh, wqkvh + (size_t)l*Cc*3*Cc, nullptr, nullptr, qkvh, NT, 3*Cc, Cc, 0);
            // attention -> half ao
            attn_kernel<<<Bb*Hh/4, 128>>>();
        }
        // proj: (NT,512)h @ (512,512)h + b -> fp32 y
        gemm_h<<<dim3(Cc/BN, NT/BM), 256, SMEM_DYN>>>(
            aoh, wprojh + (size_t)l*Cc*Cc, proj_b + (size_t)l*Cc, y, nullptr, NT, Cc, Cc, 0);
        // x = LN(x + y); writes fp32 + half
        add_ln_kernel<<<NT/8, 256>>>(y, ln1g + (size_t)l*Cc, ln1b + (size_t)l*Cc);
        // MLP up: (NT,512)h @ (512,2048)h + b, relu -> half h
        gemm_h<<<dim3(DFFd/BN, NT/BM), 256, SMEM_DYN>>>(
            xh, w1h + (size_t)l*Cc*DFFd, b1 + (size_t)l*DFFd, nullptr, hh, NT, DFFd, Cc, 1);
        // MLP down: (NT,2048)h @ (2048,512)h + b -> fp32 y
        gemm_h<<<dim3(Cc/BN, NT/BM), 256, SMEM_DYN>>>(
            hh, w2h + (size_t)l*DFFd*Cc, b2 + (size_t)l*Cc, y, nullptr, NT, Cc, DFFd, 0);
        // x = LN(x + y)
        add_ln_kernel<<<NT/8, 256>>>(y, ln2g + (size_t)l*Cc, ln2b + (size_t)l*Cc);
    }

    logits_kernel<<<NT/16, 256>>>(lm_w, lm_b, out);
}